// round 15
// baseline (speedup 1.0000x reference)
#include <cuda_runtime.h>
#include <cuda_bf16.h>
#include <cstdint>

#define BB 4
#define TE 512
#define TD 256
#define HE 128
#define HD 256
#define TT 2          // decoder steps per CTA (one f32x2 pair)

// ---- scratch (device globals; no allocation allowed) ----
__device__ float g_TWsT[BB * HE * TE];      // tanh(enc @ W_a) transposed [B,HE,TE]

typedef unsigned long long u64;

__device__ __forceinline__ float fast_tanh(float x) {
    float y; asm("tanh.approx.f32 %0, %1;" : "=f"(y) : "f"(x)); return y;
}
__device__ __forceinline__ float fast_rcp(float x) {
    float r; asm("rcp.approx.ftz.f32 %0, %1;" : "=f"(r) : "f"(x)); return r;
}
__device__ __forceinline__ u64 pk2(float a, float b) {
    u64 r; asm("mov.b64 %0, {%1, %2};" : "=l"(r) : "f"(a), "f"(b)); return r;
}
__device__ __forceinline__ void upk2(u64 p, float& a, float& b) {
    asm("mov.b64 {%0, %1}, %2;" : "=f"(a), "=f"(b) : "l"(p));
}
__device__ __forceinline__ u64 add2(u64 a, u64 b) {
    u64 r; asm("add.rn.f32x2 %0, %1, %2;" : "=l"(r) : "l"(a), "l"(b)); return r;
}
__device__ __forceinline__ u64 mul2(u64 a, u64 b) {
    u64 r; asm("mul.rn.f32x2 %0, %1, %2;" : "=l"(r) : "l"(a), "l"(b)); return r;
}
__device__ __forceinline__ u64 fma2(u64 a, u64 b, u64 c) {
    u64 r; asm("fma.rn.f32x2 %0, %1, %2, %3;" : "=l"(r) : "l"(a), "l"(b), "l"(c)); return r;
}

// ================= Prep kernel: TWsT = tanh(enc@W)^T only ==================
__global__ __launch_bounds__(128) void prep_kernel(
    const float* __restrict__ enc, const float* __restrict__ W)
{
    __shared__ float sbuf[1024];                 // 4 KB (8 enc rows)
    int tid = threadIdx.x;
    int blk = blockIdx.x;
    int b  = blk >> 6;
    int s0 = (blk & 63) * 8;

    const float4* erow = reinterpret_cast<const float4*>(enc + ((size_t)b * TE + s0) * HE);
    float4* sb4 = reinterpret_cast<float4*>(sbuf);
#pragma unroll
    for (int i = 0; i < 2; i++) sb4[tid + 128 * i] = erow[tid + 128 * i];
    __syncthreads();

    float acc[8];
#pragma unroll
    for (int r = 0; r < 8; r++) acc[r] = 0.f;
#pragma unroll 4
    for (int k = 0; k < HE; k += 4) {
        float w0 = W[(k + 0) * HE + tid];
        float w1 = W[(k + 1) * HE + tid];
        float w2 = W[(k + 2) * HE + tid];
        float w3 = W[(k + 3) * HE + tid];
#pragma unroll
        for (int r = 0; r < 8; r++) {
            float aa = acc[r];
            aa = fmaf(sbuf[r * HE + k + 0], w0, aa);
            aa = fmaf(sbuf[r * HE + k + 1], w1, aa);
            aa = fmaf(sbuf[r * HE + k + 2], w2, aa);
            aa = fmaf(sbuf[r * HE + k + 3], w3, aa);
            acc[r] = aa;
        }
    }
    size_t base = ((size_t)b * HE + tid) * TE + s0;   // [b][f=tid][s0+r]
#pragma unroll
    for (int r = 0; r < 8; r++) g_TWsT[base + r] = fast_tanh(acc[r]);
}

// ===== Fused: inline TUh + score (identity, f32x2) + softmax + context =====
// grid 512 = (b, t-pair). 512 threads. Thread owns encoder position s = tid.
__global__ __launch_bounds__(512, 3) void score_ctx_kernel(
    const float* __restrict__ enc,
    const float* __restrict__ dec,
    const float* __restrict__ Ua,
    const float* __restrict__ Va,
    float* __restrict__ c_out,   // [B,TD,HE]
    float* __restrict__ e_out)   // [B,TD,TE]
{
    __shared__ float s_dec[TT * HD];             // 2 KB
    __shared__ float s_part[2 * TT * HE];        // 2 KB (half-dot partials)
    __shared__ u64   s_tu2[HE];                  // 1 KB (tu[t0], tu[t1]) per f
    __shared__ u64   s_v2[HE];                   // 1 KB (v, v) per f
    __shared__ float s_sc[TT][TE];               // 4 KB raw scores -> weights
    __shared__ float s_ctx[4][TT * HE];          // 4 KB

    int blk = blockIdx.x;
    int b  = blk >> 7;                           // blk / 128
    int t0 = (blk & 127) * TT;
    int tid  = threadIdx.x;                      // 0..511 == encoder position s
    int warp = tid >> 5;
    int lane = tid & 31;

    // ---- Phase 0: inline TUh for this CTA's 2 decoder rows ----
    s_dec[tid] = dec[((size_t)b * TD + t0) * HD + tid];   // 512 = TT*HD/... (2*256)
    if (tid < HE) {
        float v = Va[tid];
        s_v2[tid] = pk2(v, v);
    }
    __syncthreads();
    {
        int half = tid >> 8;                     // 0/1: which half of the dot
        int t    = (tid >> 7) & 1;
        int f    = tid & 127;
        const float* dr = s_dec + t * HD + half * 128;
        const float* uc = Ua + (size_t)(half * 128) * HE + f;
        float p = 0.f;
#pragma unroll 8
        for (int d = 0; d < 128; d++)
            p = fmaf(dr[d], uc[(size_t)d * HE], p);
        s_part[tid] = p;
    }
    __syncthreads();
    if (tid < TT * HE) {                          // 256 threads finish
        int t = tid >> 7, f = tid & 127;
        float tu = fast_tanh(s_part[tid] + s_part[tid + 256]);
        reinterpret_cast<float*>(&s_tu2[f])[t] = tu;
    }
    __syncthreads();

    // ---- Phase 1: scores via tanh-addition identity, f32x2 packed over t ----
    {
        const float* wcol = g_TWsT + (size_t)b * HE * TE + tid;   // + f*TE
        const u64 ONE2 = pk2(1.0f, 1.0f);
        u64 acc2 = pk2(0.f, 0.f);
#pragma unroll 4
        for (int f = 0; f < HE; f++) {
            float w = wcol[(size_t)f * TE];       // coalesced LDG.32
            u64 w2 = pk2(w, w);
            u64 u2 = s_tu2[f];                    // broadcast LDS.64
            u64 v2 = s_v2[f];
            u64 x2 = add2(w2, u2);                // w+u   (both t)
            u64 d2 = fma2(w2, u2, ONE2);          // 1+w*u
            u64 n2 = mul2(v2, x2);                // v*(w+u)
            float dlo, dhi; upk2(d2, dlo, dhi);
            u64 r2 = pk2(fast_rcp(dlo), fast_rcp(dhi));
            acc2 = fma2(n2, r2, acc2);
        }
        float a0, a1; upk2(acc2, a0, a1);
        s_sc[0][tid] = a0;
        s_sc[1][tid] = a1;
    }
    __syncthreads();

    // ---- Phase 2: softmax (warps 0..1, one per t) ----
    if (warp < TT) {
        int t = warp;
        float* sc = s_sc[t];
        float m = -1e30f;
        for (int s = lane; s < TE; s += 32) m = fmaxf(m, sc[s]);
#pragma unroll
        for (int o = 16; o > 0; o >>= 1)
            m = fmaxf(m, __shfl_xor_sync(0xFFFFFFFFu, m, o));
        float sum = 0.f;
        for (int s = lane; s < TE; s += 32) {
            float ex = __expf(sc[s] - m);
            sc[s] = ex;
            sum += ex;
        }
#pragma unroll
        for (int o = 16; o > 0; o >>= 1)
            sum += __shfl_xor_sync(0xFFFFFFFFu, sum, o);
        float inv = 1.0f / sum;
        float* eo = e_out + ((size_t)(b * TD + t0 + t)) * TE;
        for (int s = lane; s < TE; s += 32) {
            float w = sc[s] * inv;
            sc[s] = w;
            eo[s] = w;
        }
    }
    __syncthreads();

    // ---- Phase 3: context, f32x2 packed over t. 4 groups split s-range. ----
    {
        int g  = tid >> 7;                       // 0..3
        int ee = tid & 127;
        const float* encb = enc + (size_t)b * TE * HE + ee;
        u64 acc2 = pk2(0.f, 0.f);
        int sbeg = g * (TE / 4);
#pragma unroll 4
        for (int s = sbeg; s < sbeg + TE / 4; s++) {
            float x  = encb[(size_t)s * HE];     // coalesced LDG.32
            u64 wp = pk2(s_sc[0][s], s_sc[1][s]);
            acc2 = fma2(wp, pk2(x, x), acc2);
        }
        float a0, a1; upk2(acc2, a0, a1);
        s_ctx[g][0 * HE + ee] = a0;
        s_ctx[g][1 * HE + ee] = a1;
    }
    __syncthreads();

    if (tid < TT * HE) {                          // 256 threads combine + store
        int t = tid >> 7, ee = tid & 127;
        float r = s_ctx[0][t * HE + ee] + s_ctx[1][t * HE + ee]
                + s_ctx[2][t * HE + ee] + s_ctx[3][t * HE + ee];
        c_out[((size_t)(b * TD + t0 + t)) * HE + ee] = r;
    }
}

extern "C" void kernel_launch(void* const* d_in, const int* in_sizes, int n_in,
                              void* d_out, int out_size) {
    const float* enc = (const float*)d_in[0];   // [B,TE,HE]
    const float* dec = (const float*)d_in[1];   // [B,TD,HD]
    const float* Wa  = (const float*)d_in[2];   // [HE,HE]
    const float* Ua  = (const float*)d_in[3];   // [HD,HE]
    const float* Va  = (const float*)d_in[4];   // [HE,1]

    float* out   = (float*)d_out;
    float* c_out = out;                          // [B,TD,HE]
    float* e_out = out + (size_t)BB * TD * HE;   // [B,TD,TE]

    prep_kernel<<<BB * 64, 128>>>(enc, Wa);
    score_ctx_kernel<<<BB * (TD / TT), 512>>>(enc, dec, Ua, Va, c_out, e_out);
}

// round 16
// speedup vs baseline: 1.5391x; 1.5391x over previous
#include <cuda_runtime.h>
#include <cuda_bf16.h>
#include <cstdint>

#define BB 4
#define TE 512
#define TD 256
#define HE 128
#define HD 256
#define TT 4

// ---- scratch (device globals; no allocation allowed) ----
__device__ float g_TWsT[BB * HE * TE];      // tanh(enc @ W_a) transposed [B,HE,TE]
__device__ float g_TUh[BB * TD * HE];       // tanh(dec @ U_a)            [B,TD,HE]

__device__ __forceinline__ float fast_tanh(float x) {
    float y; asm("tanh.approx.f32 %0, %1;" : "=f"(y) : "f"(x)); return y;
}
__device__ __forceinline__ float fast_rcp(float x) {
    float r; asm("rcp.approx.ftz.f32 %0, %1;" : "=f"(r) : "f"(x)); return r;
}

// ====== Prep: TUh = tanh(dec@U), TWsT = tanh(enc@W)^T.  k-split, 256 thr ====
// blocks [0,256):   Uh, 4 decoder rows, k halved across thread-groups
// blocks [256,512): Ws, 8 encoder rows, k halved across thread-groups
__global__ __launch_bounds__(256) void prep_kernel(
    const float* __restrict__ dec, const float* __restrict__ U,
    const float* __restrict__ enc, const float* __restrict__ W)
{
    __shared__ float sbuf[1024];                 // 4 KB staged input rows
    __shared__ float spart[1024];                // 4 KB k-split partials
    int tid = threadIdx.x;                       // 0..255
    int h   = tid >> 7;                          // k-half
    int f   = tid & 127;                         // output feature

    if (blockIdx.x < 256) {
        // ---- Uh: rows = B*TD, 4 per block, k in [h*128, h*128+128) ----
        int blk = blockIdx.x;
        int b  = blk >> 6;
        int t0 = (blk & 63) * 4;
        const float4* drow = reinterpret_cast<const float4*>(dec + ((size_t)b * TD + t0) * HD);
        reinterpret_cast<float4*>(sbuf)[tid] = drow[tid];   // 4*256 floats
        __syncthreads();

        float a0 = 0.f, a1 = 0.f, a2 = 0.f, a3 = 0.f;
        int kb = h * 128;
#pragma unroll 8
        for (int k = kb; k < kb + 128; k += 2) {
            float u0 = U[(k + 0) * HE + f];
            float u1 = U[(k + 1) * HE + f];
            a0 = fmaf(sbuf[0 * HD + k], u0, a0); a0 = fmaf(sbuf[0 * HD + k + 1], u1, a0);
            a1 = fmaf(sbuf[1 * HD + k], u0, a1); a1 = fmaf(sbuf[1 * HD + k + 1], u1, a1);
            a2 = fmaf(sbuf[2 * HD + k], u0, a2); a2 = fmaf(sbuf[2 * HD + k + 1], u1, a2);
            a3 = fmaf(sbuf[3 * HD + k], u0, a3); a3 = fmaf(sbuf[3 * HD + k + 1], u1, a3);
        }
        if (h == 1) {
            spart[0 * HE + f] = a0; spart[1 * HE + f] = a1;
            spart[2 * HE + f] = a2; spart[3 * HE + f] = a3;
        }
        __syncthreads();
        if (h == 0) {
            size_t base = ((size_t)(b * TD + t0)) * HE + f;
            g_TUh[base + 0 * HE] = fast_tanh(a0 + spart[0 * HE + f]);
            g_TUh[base + 1 * HE] = fast_tanh(a1 + spart[1 * HE + f]);
            g_TUh[base + 2 * HE] = fast_tanh(a2 + spart[2 * HE + f]);
            g_TUh[base + 3 * HE] = fast_tanh(a3 + spart[3 * HE + f]);
        }
    } else {
        // ---- Ws: rows = B*TE, 8 per block, k in [h*64, h*64+64) ----
        int blk = blockIdx.x - 256;
        int b  = blk >> 6;
        int s0 = (blk & 63) * 8;
        const float4* erow = reinterpret_cast<const float4*>(enc + ((size_t)b * TE + s0) * HE);
        reinterpret_cast<float4*>(sbuf)[tid] = erow[tid];   // 8*128 floats
        __syncthreads();

        float acc[8];
#pragma unroll
        for (int r = 0; r < 8; r++) acc[r] = 0.f;
        int kb = h * 64;
#pragma unroll 4
        for (int k = kb; k < kb + 64; k += 2) {
            float w0 = W[(k + 0) * HE + f];
            float w1 = W[(k + 1) * HE + f];
#pragma unroll
            for (int r = 0; r < 8; r++) {
                float aa = acc[r];
                aa = fmaf(sbuf[r * HE + k], w0, aa);
                aa = fmaf(sbuf[r * HE + k + 1], w1, aa);
                acc[r] = aa;
            }
        }
        if (h == 1) {
#pragma unroll
            for (int r = 0; r < 8; r++) spart[r * HE + f] = acc[r];
        }
        __syncthreads();
        if (h == 0) {
            size_t base = ((size_t)b * HE + f) * TE + s0;   // transposed [b][f][s]
#pragma unroll
            for (int r = 0; r < 8; r++)
                g_TWsT[base + r] = fast_tanh(acc[r] + spart[r * HE + f]);
        }
    }
}

// ====== Fused score/softmax/context: identity + pairwise reciprocal ======
// One CTA per (b, tile of TT=4 decoder steps). 512 threads. Thread = one s.
__global__ __launch_bounds__(512, 2) void score_ctx_kernel(
    const float* __restrict__ enc,
    const float* __restrict__ Va,
    float* __restrict__ c_out,   // [B,TD,HE]
    float* __restrict__ e_out)   // [B,TD,TE]
{
    __shared__ float s_tu[TT * HE];              // 2 KB
    __shared__ float s_v[HE];                    // 0.5 KB
    __shared__ float s_scores[TT * TE];          // 8 KB
    __shared__ float s_ctx[4][TT * HE];          // 8 KB

    int blk = blockIdx.x;
    int b  = blk / (TD / TT);
    int t0 = (blk % (TD / TT)) * TT;
    int tid  = threadIdx.x;                      // 0..511 == encoder position s
    int warp = tid >> 5;
    int lane = tid & 31;

    s_tu[tid & 511] = g_TUh[((size_t)(b * TD + t0)) * HE + tid];
    if (tid < HE) s_v[tid] = Va[tid];
    __syncthreads();

    const float4* tu4 = reinterpret_cast<const float4*>(s_tu);
    const float4* v4p = reinterpret_cast<const float4*>(s_v);

    // ---- Phase 1: tanh(w+u) = (w+u)/(1+w*u); rcp shared across t-pairs ----
    {
        const float* wcol = g_TWsT + (size_t)b * HE * TE + tid;   // + f*TE
        float acc[TT];
#pragma unroll
        for (int t = 0; t < TT; t++) acc[t] = 0.f;

#pragma unroll 8
        for (int q = 0; q < HE / 4; q++) {
            float wx = wcol[(4 * q + 0) * TE];
            float wy = wcol[(4 * q + 1) * TE];
            float wz = wcol[(4 * q + 2) * TE];
            float ww = wcol[(4 * q + 3) * TE];
            float4 v = v4p[q];
#pragma unroll
            for (int tp = 0; tp < TT; tp += 2) {
                float4 u0 = tu4[(tp + 0) * (HE / 4) + q];
                float4 u1 = tu4[(tp + 1) * (HE / 4) + q];
                float a0 = acc[tp], a1 = acc[tp + 1];
                // component x
                {
                    float d0 = fmaf(wx, u0.x, 1.0f), d1 = fmaf(wx, u1.x, 1.0f);
                    float r  = fast_rcp(d0 * d1);
                    a0 = fmaf(v.x * (wx + u0.x), r * d1, a0);
                    a1 = fmaf(v.x * (wx + u1.x), r * d0, a1);
                }
                // component y
                {
                    float d0 = fmaf(wy, u0.y, 1.0f), d1 = fmaf(wy, u1.y, 1.0f);
                    float r  = fast_rcp(d0 * d1);
                    a0 = fmaf(v.y * (wy + u0.y), r * d1, a0);
                    a1 = fmaf(v.y * (wy + u1.y), r * d0, a1);
                }
                // component z
                {
                    float d0 = fmaf(wz, u0.z, 1.0f), d1 = fmaf(wz, u1.z, 1.0f);
                    float r  = fast_rcp(d0 * d1);
                    a0 = fmaf(v.z * (wz + u0.z), r * d1, a0);
                    a1 = fmaf(v.z * (wz + u1.z), r * d0, a1);
                }
                // component w
                {
                    float d0 = fmaf(ww, u0.w, 1.0f), d1 = fmaf(ww, u1.w, 1.0f);
                    float r  = fast_rcp(d0 * d1);
                    a0 = fmaf(v.w * (ww + u0.w), r * d1, a0);
                    a1 = fmaf(v.w * (ww + u1.w), r * d0, a1);
                }
                acc[tp] = a0; acc[tp + 1] = a1;
            }
        }
#pragma unroll
        for (int t = 0; t < TT; t++)
            s_scores[t * TE + tid] = acc[t];
    }
    __syncthreads();

    // ---- Phase 2: softmax per decoder step (warps 0..3) ----
    if (warp < TT) {
        int t = warp;
        float* sc = s_scores + t * TE;
        float m = -1e30f;
        for (int s = lane; s < TE; s += 32) m = fmaxf(m, sc[s]);
#pragma unroll
        for (int o = 16; o > 0; o >>= 1)
            m = fmaxf(m, __shfl_xor_sync(0xFFFFFFFFu, m, o));
        float sum = 0.f;
        for (int s = lane; s < TE; s += 32) {
            float ex = __expf(sc[s] - m);
            sc[s] = ex;
            sum += ex;
        }
#pragma unroll
        for (int o = 16; o > 0; o >>= 1)
            sum += __shfl_xor_sync(0xFFFFFFFFu, sum, o);
        float inv = 1.0f / sum;
        float* eo = e_out + ((size_t)(b * TD + t0 + t)) * TE;
        for (int s = lane; s < TE; s += 32) {
            float w = sc[s] * inv;
            sc[s] = w;
            eo[s] = w;
        }
    }
    __syncthreads();

    // ---- Phase 3: context. 4 groups of 128 threads split the s-range. ----
    {
        int g  = tid >> 7;              // 0..3
        int ee = tid & 127;             // output feature
        const float* encb = enc + (size_t)b * TE * HE;
        float a0 = 0.f, a1 = 0.f, a2 = 0.f, a3 = 0.f;
        int sbeg = g * (TE / 4);
#pragma unroll 2
        for (int s = sbeg; s < sbeg + TE / 4; s += 4) {
            float4 w0 = *reinterpret_cast<const float4*>(&s_scores[0 * TE + s]);
            float4 w1 = *reinterpret_cast<const float4*>(&s_scores[1 * TE + s]);
            float4 w2 = *reinterpret_cast<const float4*>(&s_scores[2 * TE + s]);
            float4 w3 = *reinterpret_cast<const float4*>(&s_scores[3 * TE + s]);
            float x0 = encb[(size_t)(s + 0) * HE + ee];
            float x1 = encb[(size_t)(s + 1) * HE + ee];
            float x2 = encb[(size_t)(s + 2) * HE + ee];
            float x3 = encb[(size_t)(s + 3) * HE + ee];
            a0 = fmaf(w0.x, x0, fmaf(w0.y, x1, fmaf(w0.z, x2, fmaf(w0.w, x3, a0))));
            a1 = fmaf(w1.x, x0, fmaf(w1.y, x1, fmaf(w1.z, x2, fmaf(w1.w, x3, a1))));
            a2 = fmaf(w2.x, x0, fmaf(w2.y, x1, fmaf(w2.z, x2, fmaf(w2.w, x3, a2))));
            a3 = fmaf(w3.x, x0, fmaf(w3.y, x1, fmaf(w3.z, x2, fmaf(w3.w, x3, a3))));
        }
        s_ctx[g][0 * HE + ee] = a0;
        s_ctx[g][1 * HE + ee] = a1;
        s_ctx[g][2 * HE + ee] = a2;
        s_ctx[g][3 * HE + ee] = a3;
    }
    __syncthreads();

    {
        float r = s_ctx[0][tid] + s_ctx[1][tid] + s_ctx[2][tid] + s_ctx[3][tid];
        int tt = tid >> 7;
        int ee = tid & 127;
        c_out[((size_t)(b * TD + t0 + tt)) * HE + ee] = r;
    }
}

extern "C" void kernel_launch(void* const* d_in, const int* in_sizes, int n_in,
                              void* d_out, int out_size) {
    const float* enc = (const float*)d_in[0];   // [B,TE,HE]
    const float* dec = (const float*)d_in[1];   // [B,TD,HD]
    const float* Wa  = (const float*)d_in[2];   // [HE,HE]
    const float* Ua  = (const float*)d_in[3];   // [HD,HE]
    const float* Va  = (const float*)d_in[4];   // [HE,1]

    float* out   = (float*)d_out;
    float* c_out = out;                          // [B,TD,HE]
    float* e_out = out + (size_t)BB * TD * HE;   // [B,TD,TE]

    prep_kernel<<<512, 256>>>(dec, Ua, enc, Wa);
    score_ctx_kernel<<<BB * (TD / TT), 512>>>(enc, Va, c_out, e_out);
}